// round 6
// baseline (speedup 1.0000x reference)
#include <cuda_runtime.h>
#include <stdint.h>
#include <math.h>

#define BB     64
#define NCH    129
#define NT     200
#define DM     256
#define DSTATE 16
#define HD     32
#define NL     4
#define DI     512
#define NH     16
#define CONVD  544
#define DPROJ  1072
#define TOK    (BB*NT)   // 12800
#define KPAD   144
#define SMS    20
#define TTILE  20

#define NW_IN  (NL*DPROJ*DM)   // rounded in_proj weights
#define NW_OUT (NL*DM*DI)      // rounded out_proj weights

// ---------------- scratch ---------------------------------------------------
__device__ float g_xsr[TOK*KPAD];
__device__ float g_mixw[DM*KPAD];
__device__ float g_biasenc[DM];
__device__ float g_h[TOK*DM];
__device__ float g_zx[TOK*DPROJ];
__device__ float g_xbc[TOK*CONVD];
__device__ float g_dt[TOK*NH];
__device__ float g_dA[TOK*NH];
__device__ float g_y[TOK*DI];
__device__ float g_o[TOK*DM];
__device__ float g_wrnd[NW_IN + NW_OUT];

// ---------------- helpers ---------------------------------------------------
__device__ __forceinline__ float blockReduceSum(float v, volatile float* sh) {
    __syncthreads();
    int lane = threadIdx.x & 31, wid = threadIdx.x >> 5;
#pragma unroll
    for (int o = 16; o > 0; o >>= 1) v += __shfl_xor_sync(0xffffffffu, v, o);
    if (lane == 0) sh[wid] = v;
    __syncthreads();
    float tot = 0.f;
    int nw = blockDim.x >> 5;
    for (int i = 0; i < nw; i++) tot += sh[i];
    return tot;
}

__device__ __forceinline__ float siluf(float x) { return x / (1.f + expf(-x)); }

__device__ __forceinline__ float tf32r(float x) {   // round-to-nearest tf32, as float
    uint32_t r; asm("cvt.rna.tf32.f32 %0, %1;" : "=r"(r) : "f"(x));
    return __uint_as_float(r);
}
__device__ __forceinline__ void mma_tf32(float* c, const uint32_t* a, const uint32_t* b) {
    asm volatile("mma.sync.aligned.m16n8k8.row.col.f32.tf32.tf32.f32 "
        "{%0,%1,%2,%3}, {%4,%5,%6,%7}, {%8,%9}, {%0,%1,%2,%3};"
        : "+f"(c[0]), "+f"(c[1]), "+f"(c[2]), "+f"(c[3])
        : "r"(a[0]), "r"(a[1]), "r"(a[2]), "r"(a[3]), "r"(b[0]), "r"(b[1]));
}
__device__ __forceinline__ void cpa16(uint32_t dst, const void* src, int sz) {
    asm volatile("cp.async.ca.shared.global [%0], [%1], 16, %2;"
                 :: "r"(dst), "l"(src), "r"(sz));
}

// ---------------- TF32 GEMM (inputs pre-rounded; raw-bit fragments) ---------
__global__ void __launch_bounds__(256, 2)
gemm_tf32(const float* __restrict__ A, const float* __restrict__ W,
          const float* __restrict__ bias, float* __restrict__ C,
          int M, int N, int K) {
    __shared__ float As[2][128 * SMS];
    __shared__ float Bs[2][128 * SMS];
    const int bm = blockIdx.y * 128, bn = blockIdx.x * 128;
    const int tid = threadIdx.x, lane = tid & 31, warp = tid >> 5;
    const int wm = (warp & 1) * 64, wn = (warp >> 1) * 32;
    const int r0 = lane >> 2, c0 = lane & 3;

    float acc[4][4][4];
#pragma unroll
    for (int i = 0; i < 4; i++)
#pragma unroll
        for (int j = 0; j < 4; j++)
#pragma unroll
            for (int k = 0; k < 4; k++) acc[i][j][k] = 0.f;

    const int lr = tid >> 2, lc = (tid & 3) * 4;
    const float* Ap0 = A + (size_t)(bm + lr) * K + lc;
    const float* Ap1 = A + (size_t)(bm + lr + 64) * K + lc;
    const int bnr0 = bn + lr, bnr1 = bn + lr + 64;
    const float* Bp0 = W + (size_t)(bnr0 < N ? bnr0 : 0) * K + lc;
    const float* Bp1 = W + (size_t)(bnr1 < N ? bnr1 : 0) * K + lc;
    const int szb0 = bnr0 < N ? 16 : 0, szb1 = bnr1 < N ? 16 : 0;

    uint32_t aAs[2], aBs[2];
    aAs[0] = (uint32_t)__cvta_generic_to_shared(&As[0][0]);
    aAs[1] = (uint32_t)__cvta_generic_to_shared(&As[1][0]);
    aBs[0] = (uint32_t)__cvta_generic_to_shared(&Bs[0][0]);
    aBs[1] = (uint32_t)__cvta_generic_to_shared(&Bs[1][0]);
    const uint32_t dof0 = (uint32_t)(lr * SMS + lc) * 4u;
    const uint32_t dof1 = (uint32_t)((lr + 64) * SMS + lc) * 4u;

    const int KT = K >> 4;

#define LOADT(kt, buf)                                                \
    do {                                                              \
        int ko = (kt) * 16;                                           \
        cpa16(aAs[buf] + dof0, Ap0 + ko, 16);                         \
        cpa16(aAs[buf] + dof1, Ap1 + ko, 16);                         \
        cpa16(aBs[buf] + dof0, Bp0 + ko, szb0);                       \
        cpa16(aBs[buf] + dof1, Bp1 + ko, szb1);                       \
        asm volatile("cp.async.commit_group;");                       \
    } while (0)

    LOADT(0, 0);
    for (int kt = 0; kt < KT; kt++) {
        asm volatile("cp.async.wait_group 0;");
        __syncthreads();
        if (kt + 1 < KT) LOADT(kt + 1, (kt + 1) & 1);
        const int buf = kt & 1;
#pragma unroll
        for (int ks = 0; ks < 2; ks++) {
            uint32_t af[4][4], bf[4][2];
#pragma unroll
            for (int mi = 0; mi < 4; mi++) {
                const float* p = &As[buf][(wm + mi * 16 + r0) * SMS + ks * 8 + c0];
                af[mi][0] = __float_as_uint(p[0]);
                af[mi][1] = __float_as_uint(p[8 * SMS]);
                af[mi][2] = __float_as_uint(p[4]);
                af[mi][3] = __float_as_uint(p[8 * SMS + 4]);
            }
#pragma unroll
            for (int nj = 0; nj < 4; nj++) {
                const float* p = &Bs[buf][(wn + nj * 8 + r0) * SMS + ks * 8 + c0];
                bf[nj][0] = __float_as_uint(p[0]);
                bf[nj][1] = __float_as_uint(p[4]);
            }
#pragma unroll
            for (int mi = 0; mi < 4; mi++)
#pragma unroll
                for (int nj = 0; nj < 4; nj++)
                    mma_tf32(acc[mi][nj], af[mi], bf[nj]);
        }
    }
#undef LOADT

#pragma unroll
    for (int mi = 0; mi < 4; mi++) {
        int row = bm + wm + mi * 16 + r0;
#pragma unroll
        for (int nj = 0; nj < 4; nj++) {
            int col = bn + wn + nj * 8 + c0 * 2;
            if (col < N) {
                float b0 = 0.f, b1 = 0.f;
                if (bias != nullptr) { b0 = bias[col]; b1 = bias[col + 1]; }
                float2 v0 = make_float2(acc[mi][nj][0] + b0, acc[mi][nj][1] + b1);
                float2 v1 = make_float2(acc[mi][nj][2] + b0, acc[mi][nj][3] + b1);
                *(float2*)&C[(size_t)row * N + col] = v0;
                *(float2*)&C[(size_t)(row + 8) * N + col] = v1;
            }
        }
    }
}

// ---------------- weight prep: tf32-round into scratch ----------------------
__global__ void k_roundw(const float* __restrict__ wi, const float* __restrict__ wo) {
    int idx = blockIdx.x * blockDim.x + threadIdx.x;
    if (idx < NW_IN) g_wrnd[idx] = tf32r(wi[idx]);
    else if (idx < NW_IN + NW_OUT) g_wrnd[idx] = tf32r(wo[idx - NW_IN]);
}

// ---------------- encoder ---------------------------------------------------
__global__ void k_sconv(const float* __restrict__ x, const float* __restrict__ w,
                        const float* __restrict__ bias) {
    int c = blockIdx.x, b = blockIdx.y, t = threadIdx.x;
    float v = 0.f;
    if (c < NCH) {
        const float* xr = x + (size_t)(b * NCH + c) * NT;
        float w0 = w[c * 3], w1 = w[c * 3 + 1], w2 = w[c * 3 + 2];
        float xm = (t > 0) ? xr[t - 1] : 0.f;
        float x0 = xr[t];
        float xp = (t < NT - 1) ? xr[t + 1] : 0.f;
        v = tf32r(xm * w0 + x0 * w1 + xp * w2 + bias[c]);
    }
    g_xsr[(size_t)(b * NT + t) * KPAD + c] = v;
}

__global__ void k_mixprep(const float* __restrict__ mw) {
    int idx = blockIdx.x * blockDim.x + threadIdx.x;
    if (idx >= DM * KPAD) return;
    int d = idx / KPAD, k = idx % KPAD;
    g_mixw[idx] = (k < NCH) ? tf32r(mw[d * NCH + k]) : 0.f;
}

__global__ void k_biasenc(const float* __restrict__ emb, const float* __restrict__ mb) {
    int d = threadIdx.x;
    float s = 0.f;
    for (int c = 0; c < NCH; c++) s += emb[c * DM + d];
    g_biasenc[d] = mb[d] + s * (1.f / NCH);
}

// ---------------- layernorm (stores tf32-rounded output) --------------------
__global__ void k_ln(const float* __restrict__ in, const float* __restrict__ res,
                     const float* __restrict__ w, const float* __restrict__ b,
                     float* __restrict__ out) {
    __shared__ float sh[8];
    int row = blockIdx.x, tid = threadIdx.x;
    float v = in[(size_t)row * DM + tid];
    if (res != nullptr) v += res[(size_t)row * DM + tid];
    float mean = blockReduceSum(v, sh) * (1.f / DM);
    float d = v - mean;
    float var = blockReduceSum(d * d, sh) * (1.f / DM);
    out[(size_t)row * DM + tid] = tf32r(d * rsqrtf(var + 1e-5f) * w[tid] + b[tid]);
}

// ---------------- conv (rolling window) + fused dt ---------------------------
// grid (5, BB), block 128. Thread c streams all 200 timesteps for one channel.
__global__ void k_conv2(const float* __restrict__ cw, const float* __restrict__ cb,
                        const float* __restrict__ dtb, const float* __restrict__ alog) {
    const int c = blockIdx.x * 128 + threadIdx.x;
    const int b = blockIdx.y;
    const bool cvalid = c < CONVD;
    const bool dtl = (c < NH);
    float w0 = 0, w1 = 0, w2 = 0, w3 = 0, bc = 0;
    if (cvalid) { w0 = cw[c*4]; w1 = cw[c*4+1]; w2 = cw[c*4+2]; w3 = cw[c*4+3]; bc = cb[c]; }
    float db = 0.f, Ae = 0.f;
    if (dtl) { db = dtb[c]; Ae = expf(alog[c]); }

    const float* zrow = g_zx + (size_t)(b * NT) * DPROJ;
    float* orow = g_xbc + (size_t)(b * NT) * CONVD;
    float p0 = 0.f, p1 = 0.f, p2 = 0.f;

    for (int t = 0; t < NT; t += 4) {
        float v0 = 0, v1 = 0, v2 = 0, v3 = 0;
        if (cvalid) {
            v0 = zrow[(size_t)(t + 0) * DPROJ + DI + c];
            v1 = zrow[(size_t)(t + 1) * DPROJ + DI + c];
            v2 = zrow[(size_t)(t + 2) * DPROJ + DI + c];
            v3 = zrow[(size_t)(t + 3) * DPROJ + DI + c];
        }
        float r0 = 0, r1 = 0, r2 = 0, r3 = 0;
        if (dtl) {
            r0 = zrow[(size_t)(t + 0) * DPROJ + DI + CONVD + c];
            r1 = zrow[(size_t)(t + 1) * DPROJ + DI + CONVD + c];
            r2 = zrow[(size_t)(t + 2) * DPROJ + DI + CONVD + c];
            r3 = zrow[(size_t)(t + 3) * DPROJ + DI + CONVD + c];
        }
        if (cvalid) {
            float o0 = bc + w0*p0 + w1*p1 + w2*p2 + w3*v0;
            float o1 = bc + w0*p1 + w1*p2 + w2*v0 + w3*v1;
            float o2 = bc + w0*p2 + w1*v0 + w2*v1 + w3*v2;
            float o3 = bc + w0*v0 + w1*v1 + w2*v2 + w3*v3;
            orow[(size_t)(t + 0) * CONVD + c] = siluf(o0);
            orow[(size_t)(t + 1) * CONVD + c] = siluf(o1);
            orow[(size_t)(t + 2) * CONVD + c] = siluf(o2);
            orow[(size_t)(t + 3) * CONVD + c] = siluf(o3);
            p0 = v1; p1 = v2; p2 = v3;
        }
        if (dtl) {
            int bt = b * NT + t;
#pragma unroll
            for (int q = 0; q < 4; q++) {
                float raw = (q == 0 ? r0 : q == 1 ? r1 : q == 2 ? r2 : r3) + db;
                float d = raw > 20.f ? raw : log1pf(expf(raw));
                g_dt[(bt + q) * NH + c] = d;
                g_dA[(bt + q) * NH + c] = expf(-d * Ae);
            }
        }
    }
}

// -------- time-tiled SSM scan with fused silu(z) gate ------------------------
__global__ void k_scan3(const float* __restrict__ Dsk) {
    const int b = blockIdx.x, half = blockIdx.y;
    const int tid = threadIdx.x;                // 256
    const int h = tid >> 4, p = (tid & 15) + half * 16;
    __shared__ float sB[TTILE][16], sC[TTILE][16];
    __shared__ float sA[TTILE][16], sT[TTILE][16];

    float st[DSTATE];
#pragma unroll
    for (int n = 0; n < DSTATE; n++) st[n] = 0.f;
    const float Dh = Dsk[h];
    const int base = b * NT;
    const size_t xoff = (size_t)h * HD + p;

    for (int t0 = 0; t0 < NT; t0 += TTILE) {
        float xv[TTILE], zv[TTILE];
#pragma unroll
        for (int tl = 0; tl < TTILE; tl++) {
            xv[tl] = __ldg(g_xbc + (size_t)(base + t0 + tl) * CONVD + xoff);
            zv[tl] = __ldg(g_zx + (size_t)(base + t0 + tl) * DPROJ + xoff);
        }

        __syncthreads();
#pragma unroll
        for (int i = tid; i < TTILE * 64; i += 256) {
            const int tl = i >> 6, j = i & 63;
            const int bt = base + t0 + tl;
            if (j < 32) {
                float v = g_xbc[(size_t)bt * CONVD + DI + j];
                if (j < 16) sB[tl][j] = v; else sC[tl][j - 16] = v;
            } else if (j < 48) {
                sA[tl][j - 32] = g_dA[bt * NH + (j - 32)];
            } else {
                sT[tl][j - 48] = g_dt[bt * NH + (j - 48)];
            }
        }
        __syncthreads();

#pragma unroll
        for (int tl = 0; tl < TTILE; tl++) {
            const float xp = xv[tl];
            const float dAh = sA[tl][h];
            const float dtx = sT[tl][h] * xp;
            float a0 = 0.f, a1 = 0.f;
#pragma unroll
            for (int n = 0; n < DSTATE; n += 2) {
                st[n]     = fmaf(dAh, st[n],     dtx * sB[tl][n]);
                st[n + 1] = fmaf(dAh, st[n + 1], dtx * sB[tl][n + 1]);
                a0 = fmaf(st[n],     sC[tl][n],     a0);
                a1 = fmaf(st[n + 1], sC[tl][n + 1], a1);
            }
            g_y[(size_t)(base + t0 + tl) * DI + xoff] =
                (a0 + a1 + xp * Dh) * siluf(zv[tl]);
        }
    }
}

// plain RMSNorm over 512 (input already gated); stores tf32-rounded
__global__ void k_rms(const float* __restrict__ nw) {
    __shared__ float sh[8];
    int row = blockIdx.x, tid = threadIdx.x;
    float y0 = g_y[(size_t)row * DI + tid];
    float y1 = g_y[(size_t)row * DI + 256 + tid];
    float ss = blockReduceSum(y0 * y0 + y1 * y1, sh);
    float sc = rsqrtf(ss * (1.f / DI) + 1e-5f);
    g_y[(size_t)row * DI + tid]       = tf32r(y0 * sc * nw[tid]);
    g_y[(size_t)row * DI + 256 + tid] = tf32r(y1 * sc * nw[256 + tid]);
}

// ---------------- fused pool + head -----------------------------------------
__global__ void k_poolhead(const float* __restrict__ w1, const float* __restrict__ b1,
                           const float* __restrict__ w2, const float* __restrict__ b2,
                           float* __restrict__ out) {
    __shared__ float sp[DM];
    __shared__ float sh[4];
    int b = blockIdx.x, tid = threadIdx.x;    // 256
    float s = 0.f;
    for (int t = 0; t < NT; t++) s += g_h[(size_t)(b * NT + t) * DM + tid];
    sp[tid] = s * (1.f / NT);
    __syncthreads();
    if (tid < 128) {
        float acc = b1[tid];
        const float* wr = w1 + tid * DM;
#pragma unroll 8
        for (int k = 0; k < DM; k++) acc = fmaf(sp[k], wr[k], acc);
        float r = fmaxf(acc, 0.f) * w2[tid];
#pragma unroll
        for (int o = 16; o > 0; o >>= 1) r += __shfl_xor_sync(0xffffffffu, r, o);
        int lane = tid & 31, wid = tid >> 5;
        if (lane == 0) sh[wid] = r;
    }
    __syncthreads();
    if (tid == 0) out[b] = sh[0] + sh[1] + sh[2] + sh[3] + b2[0];
}

// ---------------- launch -----------------------------------------------------
extern "C" void kernel_launch(void* const* d_in, const int* in_sizes, int n_in,
                              void* d_out, int out_size) {
    const float* x         = (const float*)d_in[0];
    const float* emb       = (const float*)d_in[1];
    const float* sconv_w   = (const float*)d_in[2];
    const float* sconv_b   = (const float*)d_in[3];
    const float* mixer_w   = (const float*)d_in[4];
    const float* mixer_b   = (const float*)d_in[5];
    const float* enc_ln_w  = (const float*)d_in[6];
    const float* enc_ln_b  = (const float*)d_in[7];
    const float* in_proj_w = (const float*)d_in[8];
    const float* conv_w    = (const float*)d_in[9];
    const float* conv_b    = (const float*)d_in[10];
    const float* dt_bias   = (const float*)d_in[11];
    const float* A_log     = (const float*)d_in[12];
    const float* D_skip    = (const float*)d_in[13];
    const float* norm_w    = (const float*)d_in[14];
    const float* out_proj_w= (const float*)d_in[15];
    const float* ln_w      = (const float*)d_in[16];
    const float* ln_b      = (const float*)d_in[17];
    const float* h1w       = (const float*)d_in[18];
    const float* h1b       = (const float*)d_in[19];
    const float* h2w       = (const float*)d_in[20];
    const float* h2b       = (const float*)d_in[21];
    float* out = (float*)d_out;

    float *xsr, *mixw, *biasenc, *h, *zx, *y, *o, *wrnd;
    cudaGetSymbolAddress((void**)&xsr,     g_xsr);
    cudaGetSymbolAddress((void**)&mixw,    g_mixw);
    cudaGetSymbolAddress((void**)&biasenc, g_biasenc);
    cudaGetSymbolAddress((void**)&h,       g_h);
    cudaGetSymbolAddress((void**)&zx,      g_zx);
    cudaGetSymbolAddress((void**)&y,       g_y);
    cudaGetSymbolAddress((void**)&o,       g_o);
    cudaGetSymbolAddress((void**)&wrnd,    g_wrnd);

    // prep
    k_roundw<<<(NW_IN + NW_OUT + 255) / 256, 256>>>(in_proj_w, out_proj_w);
    k_sconv<<<dim3(KPAD, BB), NT>>>(x, sconv_w, sconv_b);
    k_mixprep<<<(DM * KPAD + 255) / 256, 256>>>(mixer_w);
    k_biasenc<<<1, DM>>>(emb, mixer_b);

    // encoder
    gemm_tf32<<<dim3(2, TOK / 128), 256>>>(xsr, mixw, biasenc, h, TOK, DM, KPAD);
    k_ln<<<TOK, DM>>>(h, nullptr, enc_ln_w, enc_ln_b, h);

    // mamba2 layers
    for (int l = 0; l < NL; l++) {
        gemm_tf32<<<dim3((DPROJ + 127) / 128, TOK / 128), 256>>>(
            h, wrnd + (size_t)l * DPROJ * DM, nullptr, zx, TOK, DPROJ, DM);
        k_conv2<<<dim3(5, BB), 128>>>(conv_w + (size_t)l * CONVD * 4,
                                      conv_b + (size_t)l * CONVD,
                                      dt_bias + l * NH, A_log + l * NH);
        k_scan3<<<dim3(BB, 2), 256>>>(D_skip + l * NH);
        k_rms<<<TOK, 256>>>(norm_w + (size_t)l * DI);
        gemm_tf32<<<dim3(2, TOK / 128), 256>>>(
            y, wrnd + NW_IN + (size_t)l * DM * DI, nullptr, o, TOK, DM, DI);
        k_ln<<<TOK, DM>>>(o, h, ln_w + l * DM, ln_b + l * DM, h);
    }

    // head
    k_poolhead<<<BB, 256>>>(h1w, h1b, h2w, h2b, out);
}

// round 7
// speedup vs baseline: 1.1834x; 1.1834x over previous
#include <cuda_runtime.h>
#include <stdint.h>
#include <math.h>

#define BB     64
#define NCH    129
#define NT     200
#define DM     256
#define DSTATE 16
#define HD     32
#define NL     4
#define DI     512
#define NH     16
#define CONVD  544
#define DPROJ  1072
#define TOK    (BB*NT)   // 12800
#define KPAD   144
#define SMS    20
#define TTILE  20
#define TSEG   25        // conv time-segment (NT % TSEG == 0)

#define NW_IN  (NL*DPROJ*DM)
#define NW_OUT (NL*DM*DI)

// ---------------- scratch ---------------------------------------------------
__device__ float g_xsr[TOK*KPAD];
__device__ float g_mixw[DM*KPAD];
__device__ float g_biasenc[DM];
__device__ float g_h[TOK*DM];
__device__ float g_zx[TOK*DPROJ];
__device__ float g_xbc[TOK*CONVD];
__device__ float g_dt[TOK*NH];
__device__ float g_dA[TOK*NH];
__device__ float g_y[TOK*DI];
__device__ float g_o[TOK*DM];
__device__ float g_wrnd[NW_IN + NW_OUT];

// ---------------- helpers ---------------------------------------------------
__device__ __forceinline__ float blockReduceSum(float v, volatile float* sh) {
    __syncthreads();
    int lane = threadIdx.x & 31, wid = threadIdx.x >> 5;
#pragma unroll
    for (int o = 16; o > 0; o >>= 1) v += __shfl_xor_sync(0xffffffffu, v, o);
    if (lane == 0) sh[wid] = v;
    __syncthreads();
    float tot = 0.f;
    int nw = blockDim.x >> 5;
    for (int i = 0; i < nw; i++) tot += sh[i];
    return tot;
}

__device__ __forceinline__ float siluf(float x) { return x / (1.f + expf(-x)); }

__device__ __forceinline__ float tf32r(float x) {
    uint32_t r; asm("cvt.rna.tf32.f32 %0, %1;" : "=r"(r) : "f"(x));
    return __uint_as_float(r);
}
__device__ __forceinline__ void mma_tf32(float* c, const uint32_t* a, const uint32_t* b) {
    asm volatile("mma.sync.aligned.m16n8k8.row.col.f32.tf32.tf32.f32 "
        "{%0,%1,%2,%3}, {%4,%5,%6,%7}, {%8,%9}, {%0,%1,%2,%3};"
        : "+f"(c[0]), "+f"(c[1]), "+f"(c[2]), "+f"(c[3])
        : "r"(a[0]), "r"(a[1]), "r"(a[2]), "r"(a[3]), "r"(b[0]), "r"(b[1]));
}
__device__ __forceinline__ void cpa16(uint32_t dst, const void* src, int sz) {
    asm volatile("cp.async.ca.shared.global [%0], [%1], 16, %2;"
                 :: "r"(dst), "l"(src), "r"(sz));
}

// ---------------- TF32 GEMM (inputs pre-rounded; raw-bit fragments) ---------
__global__ void __launch_bounds__(256, 2)
gemm_tf32(const float* __restrict__ A, const float* __restrict__ W,
          const float* __restrict__ bias, float* __restrict__ C,
          int M, int N, int K) {
    __shared__ float As[2][128 * SMS];
    __shared__ float Bs[2][128 * SMS];
    const int bm = blockIdx.y * 128, bn = blockIdx.x * 128;
    const int tid = threadIdx.x, lane = tid & 31, warp = tid >> 5;
    const int wm = (warp & 1) * 64, wn = (warp >> 1) * 32;
    const int r0 = lane >> 2, c0 = lane & 3;

    float acc[4][4][4];
#pragma unroll
    for (int i = 0; i < 4; i++)
#pragma unroll
        for (int j = 0; j < 4; j++)
#pragma unroll
            for (int k = 0; k < 4; k++) acc[i][j][k] = 0.f;

    const int lr = tid >> 2, lc = (tid & 3) * 4;
    const float* Ap0 = A + (size_t)(bm + lr) * K + lc;
    const float* Ap1 = A + (size_t)(bm + lr + 64) * K + lc;
    const int bnr0 = bn + lr, bnr1 = bn + lr + 64;
    const float* Bp0 = W + (size_t)(bnr0 < N ? bnr0 : 0) * K + lc;
    const float* Bp1 = W + (size_t)(bnr1 < N ? bnr1 : 0) * K + lc;
    const int szb0 = bnr0 < N ? 16 : 0, szb1 = bnr1 < N ? 16 : 0;

    uint32_t aAs[2], aBs[2];
    aAs[0] = (uint32_t)__cvta_generic_to_shared(&As[0][0]);
    aAs[1] = (uint32_t)__cvta_generic_to_shared(&As[1][0]);
    aBs[0] = (uint32_t)__cvta_generic_to_shared(&Bs[0][0]);
    aBs[1] = (uint32_t)__cvta_generic_to_shared(&Bs[1][0]);
    const uint32_t dof0 = (uint32_t)(lr * SMS + lc) * 4u;
    const uint32_t dof1 = (uint32_t)((lr + 64) * SMS + lc) * 4u;

    const int KT = K >> 4;

#define LOADT(kt, buf)                                                \
    do {                                                              \
        int ko = (kt) * 16;                                           \
        cpa16(aAs[buf] + dof0, Ap0 + ko, 16);                         \
        cpa16(aAs[buf] + dof1, Ap1 + ko, 16);                         \
        cpa16(aBs[buf] + dof0, Bp0 + ko, szb0);                       \
        cpa16(aBs[buf] + dof1, Bp1 + ko, szb1);                       \
        asm volatile("cp.async.commit_group;");                       \
    } while (0)

    LOADT(0, 0);
    for (int kt = 0; kt < KT; kt++) {
        asm volatile("cp.async.wait_group 0;");
        __syncthreads();
        if (kt + 1 < KT) LOADT(kt + 1, (kt + 1) & 1);
        const int buf = kt & 1;
#pragma unroll
        for (int ks = 0; ks < 2; ks++) {
            uint32_t af[4][4], bf[4][2];
#pragma unroll
            for (int mi = 0; mi < 4; mi++) {
                const float* p = &As[buf][(wm + mi * 16 + r0) * SMS + ks * 8 + c0];
                af[mi][0] = __float_as_uint(p[0]);
                af[mi][1] = __float_as_uint(p[8 * SMS]);
                af[mi][2] = __float_as_uint(p[4]);
                af[mi][3] = __float_as_uint(p[8 * SMS + 4]);
            }
#pragma unroll
            for (int nj = 0; nj < 4; nj++) {
                const float* p = &Bs[buf][(wn + nj * 8 + r0) * SMS + ks * 8 + c0];
                bf[nj][0] = __float_as_uint(p[0]);
                bf[nj][1] = __float_as_uint(p[4]);
            }
#pragma unroll
            for (int mi = 0; mi < 4; mi++)
#pragma unroll
                for (int nj = 0; nj < 4; nj++)
                    mma_tf32(acc[mi][nj], af[mi], bf[nj]);
        }
    }
#undef LOADT

#pragma unroll
    for (int mi = 0; mi < 4; mi++) {
        int row = bm + wm + mi * 16 + r0;
#pragma unroll
        for (int nj = 0; nj < 4; nj++) {
            int col = bn + wn + nj * 8 + c0 * 2;
            if (col < N) {
                float b0 = 0.f, b1 = 0.f;
                if (bias != nullptr) { b0 = bias[col]; b1 = bias[col + 1]; }
                float2 v0 = make_float2(acc[mi][nj][0] + b0, acc[mi][nj][1] + b1);
                float2 v1 = make_float2(acc[mi][nj][2] + b0, acc[mi][nj][3] + b1);
                *(float2*)&C[(size_t)row * N + col] = v0;
                *(float2*)&C[(size_t)(row + 8) * N + col] = v1;
            }
        }
    }
}

// ---------------- weight prep: tf32-round into scratch ----------------------
__global__ void k_roundw(const float* __restrict__ wi, const float* __restrict__ wo) {
    int idx = blockIdx.x * blockDim.x + threadIdx.x;
    if (idx < NW_IN) g_wrnd[idx] = tf32r(wi[idx]);
    else if (idx < NW_IN + NW_OUT) g_wrnd[idx] = tf32r(wo[idx - NW_IN]);
}

// ---------------- encoder ---------------------------------------------------
__global__ void k_sconv(const float* __restrict__ x, const float* __restrict__ w,
                        const float* __restrict__ bias) {
    int c = blockIdx.x, b = blockIdx.y, t = threadIdx.x;
    float v = 0.f;
    if (c < NCH) {
        const float* xr = x + (size_t)(b * NCH + c) * NT;
        float w0 = w[c * 3], w1 = w[c * 3 + 1], w2 = w[c * 3 + 2];
        float xm = (t > 0) ? xr[t - 1] : 0.f;
        float x0 = xr[t];
        float xp = (t < NT - 1) ? xr[t + 1] : 0.f;
        v = tf32r(xm * w0 + x0 * w1 + xp * w2 + bias[c]);
    }
    g_xsr[(size_t)(b * NT + t) * KPAD + c] = v;
}

__global__ void k_mixprep(const float* __restrict__ mw) {
    int idx = blockIdx.x * blockDim.x + threadIdx.x;
    if (idx >= DM * KPAD) return;
    int d = idx / KPAD, k = idx % KPAD;
    g_mixw[idx] = (k < NCH) ? tf32r(mw[d * NCH + k]) : 0.f;
}

// grid 32 blocks x 256 thr; warp per d (8 d per block); lane-strided sum over c
__global__ void k_biasenc(const float* __restrict__ emb, const float* __restrict__ mb) {
    int tid = threadIdx.x, lane = tid & 31, w = tid >> 5;
    int d = blockIdx.x * 8 + w;
    float s = 0.f;
    for (int c = lane; c < NCH; c += 32) s += emb[c * DM + d];
#pragma unroll
    for (int o = 16; o > 0; o >>= 1) s += __shfl_xor_sync(0xffffffffu, s, o);
    if (lane == 0) g_biasenc[d] = mb[d] + s * (1.f / NCH);
}

// ---------------- layernorm (stores tf32-rounded output) --------------------
__global__ void k_ln(const float* __restrict__ in, const float* __restrict__ res,
                     const float* __restrict__ w, const float* __restrict__ b,
                     float* __restrict__ out) {
    __shared__ float sh[8];
    int row = blockIdx.x, tid = threadIdx.x;
    float v = in[(size_t)row * DM + tid];
    if (res != nullptr) v += res[(size_t)row * DM + tid];
    float mean = blockReduceSum(v, sh) * (1.f / DM);
    float d = v - mean;
    float var = blockReduceSum(d * d, sh) * (1.f / DM);
    out[(size_t)row * DM + tid] = tf32r(d * rsqrtf(var + 1e-5f) * w[tid] + b[tid]);
}

// ---------------- dt / dA ----------------------------------------------------
__global__ void k_dt(const float* __restrict__ dtb, const float* __restrict__ alog) {
    int idx = blockIdx.x * blockDim.x + threadIdx.x;
    if (idx >= TOK * NH) return;
    int h = idx & 15, bt = idx >> 4;
    float raw = g_zx[(size_t)bt * DPROJ + DI + CONVD + h] + dtb[h];
    float d = raw > 20.f ? raw : log1pf(expf(raw));
    g_dt[idx] = d;
    g_dA[idx] = expf(-d * expf(alog[h]));
}

// ------- conv: time-parallel, register halo; grid (5, BB, NT/TSEG) ----------
__global__ void k_conv3(const float* __restrict__ cw, const float* __restrict__ cb) {
    const int c = blockIdx.x * 128 + threadIdx.x;
    const int b = blockIdx.y;
    const int t0 = blockIdx.z * TSEG;
    const bool cvalid = c < CONVD;
    float w0 = 0, w1 = 0, w2 = 0, w3 = 0, bc = 0;
    if (cvalid) { w0 = cw[c*4]; w1 = cw[c*4+1]; w2 = cw[c*4+2]; w3 = cw[c*4+3]; bc = cb[c]; }

    const float* zcol = g_zx + (size_t)(b * NT) * DPROJ + DI + c;
    float v[TSEG + 3];
#pragma unroll
    for (int i = 0; i < TSEG + 3; i++) {
        int t = t0 - 3 + i;
        v[i] = (cvalid && t >= 0) ? zcol[(size_t)t * DPROJ] : 0.f;
    }
    if (!cvalid) return;
    float* ocol = g_xbc + (size_t)(b * NT) * CONVD + c;
#pragma unroll
    for (int s = 0; s < TSEG; s++) {
        float o = bc + w0 * v[s] + w1 * v[s + 1] + w2 * v[s + 2] + w3 * v[s + 3];
        ocol[(size_t)(t0 + s) * CONVD] = siluf(o);
    }
}

// -------- time-tiled SSM scan with fused silu(z) gate ------------------------
__global__ void k_scan3(const float* __restrict__ Dsk) {
    const int b = blockIdx.x, half = blockIdx.y;
    const int tid = threadIdx.x;                // 256
    const int h = tid >> 4, p = (tid & 15) + half * 16;
    __shared__ float sB[TTILE][16], sC[TTILE][16];
    __shared__ float sA[TTILE][16], sT[TTILE][16];

    float st[DSTATE];
#pragma unroll
    for (int n = 0; n < DSTATE; n++) st[n] = 0.f;
    const float Dh = Dsk[h];
    const int base = b * NT;
    const size_t xoff = (size_t)h * HD + p;

    for (int t0 = 0; t0 < NT; t0 += TTILE) {
        float xv[TTILE], zv[TTILE];
#pragma unroll
        for (int tl = 0; tl < TTILE; tl++) {
            xv[tl] = __ldg(g_xbc + (size_t)(base + t0 + tl) * CONVD + xoff);
            zv[tl] = __ldg(g_zx + (size_t)(base + t0 + tl) * DPROJ + xoff);
        }

        __syncthreads();
#pragma unroll
        for (int i = tid; i < TTILE * 64; i += 256) {
            const int tl = i >> 6, j = i & 63;
            const int bt = base + t0 + tl;
            if (j < 32) {
                float v = g_xbc[(size_t)bt * CONVD + DI + j];
                if (j < 16) sB[tl][j] = v; else sC[tl][j - 16] = v;
            } else if (j < 48) {
                sA[tl][j - 32] = g_dA[bt * NH + (j - 32)];
            } else {
                sT[tl][j - 48] = g_dt[bt * NH + (j - 48)];
            }
        }
        __syncthreads();

#pragma unroll
        for (int tl = 0; tl < TTILE; tl++) {
            const float xp = xv[tl];
            const float dAh = sA[tl][h];
            const float dtx = sT[tl][h] * xp;
            float a0 = 0.f, a1 = 0.f;
#pragma unroll
            for (int n = 0; n < DSTATE; n += 2) {
                st[n]     = fmaf(dAh, st[n],     dtx * sB[tl][n]);
                st[n + 1] = fmaf(dAh, st[n + 1], dtx * sB[tl][n + 1]);
                a0 = fmaf(st[n],     sC[tl][n],     a0);
                a1 = fmaf(st[n + 1], sC[tl][n + 1], a1);
            }
            g_y[(size_t)(base + t0 + tl) * DI + xoff] =
                (a0 + a1 + xp * Dh) * siluf(zv[tl]);
        }
    }
}

// plain RMSNorm over 512 (input already gated); stores tf32-rounded
__global__ void k_rms(const float* __restrict__ nw) {
    __shared__ float sh[8];
    int row = blockIdx.x, tid = threadIdx.x;
    float y0 = g_y[(size_t)row * DI + tid];
    float y1 = g_y[(size_t)row * DI + 256 + tid];
    float ss = blockReduceSum(y0 * y0 + y1 * y1, sh);
    float sc = rsqrtf(ss * (1.f / DI) + 1e-5f);
    g_y[(size_t)row * DI + tid]       = tf32r(y0 * sc * nw[tid]);
    g_y[(size_t)row * DI + 256 + tid] = tf32r(y1 * sc * nw[256 + tid]);
}

// ---------------- fused pool + head -----------------------------------------
__global__ void k_poolhead(const float* __restrict__ w1, const float* __restrict__ b1,
                           const float* __restrict__ w2, const float* __restrict__ b2,
                           float* __restrict__ out) {
    __shared__ float sp[DM];
    __shared__ float sh[4];
    int b = blockIdx.x, tid = threadIdx.x;    // 256
    float s = 0.f;
    for (int t = 0; t < NT; t++) s += g_h[(size_t)(b * NT + t) * DM + tid];
    sp[tid] = s * (1.f / NT);
    __syncthreads();
    if (tid < 128) {
        float acc = b1[tid];
        const float* wr = w1 + tid * DM;
#pragma unroll 8
        for (int k = 0; k < DM; k++) acc = fmaf(sp[k], wr[k], acc);
        float r = fmaxf(acc, 0.f) * w2[tid];
#pragma unroll
        for (int o = 16; o > 0; o >>= 1) r += __shfl_xor_sync(0xffffffffu, r, o);
        int lane = tid & 31, wid = tid >> 5;
        if (lane == 0) sh[wid] = r;
    }
    __syncthreads();
    if (tid == 0) out[b] = sh[0] + sh[1] + sh[2] + sh[3] + b2[0];
}

// ---------------- launch -----------------------------------------------------
extern "C" void kernel_launch(void* const* d_in, const int* in_sizes, int n_in,
                              void* d_out, int out_size) {
    const float* x         = (const float*)d_in[0];
    const float* emb       = (const float*)d_in[1];
    const float* sconv_w   = (const float*)d_in[2];
    const float* sconv_b   = (const float*)d_in[3];
    const float* mixer_w   = (const float*)d_in[4];
    const float* mixer_b   = (const float*)d_in[5];
    const float* enc_ln_w  = (const float*)d_in[6];
    const float* enc_ln_b  = (const float*)d_in[7];
    const float* in_proj_w = (const float*)d_in[8];
    const float* conv_w    = (const float*)d_in[9];
    const float* conv_b    = (const float*)d_in[10];
    const float* dt_bias   = (const float*)d_in[11];
    const float* A_log     = (const float*)d_in[12];
    const float* D_skip    = (const float*)d_in[13];
    const float* norm_w    = (const float*)d_in[14];
    const float* out_proj_w= (const float*)d_in[15];
    const float* ln_w      = (const float*)d_in[16];
    const float* ln_b      = (const float*)d_in[17];
    const float* h1w       = (const float*)d_in[18];
    const float* h1b       = (const float*)d_in[19];
    const float* h2w       = (const float*)d_in[20];
    const float* h2b       = (const float*)d_in[21];
    float* out = (float*)d_out;

    float *xsr, *mixw, *h, *zx, *y, *o, *wrnd;
    cudaGetSymbolAddress((void**)&xsr,  g_xsr);
    cudaGetSymbolAddress((void**)&mixw, g_mixw);
    cudaGetSymbolAddress((void**)&h,    g_h);
    cudaGetSymbolAddress((void**)&zx,   g_zx);
    cudaGetSymbolAddress((void**)&y,    g_y);
    cudaGetSymbolAddress((void**)&o,    g_o);
    cudaGetSymbolAddress((void**)&wrnd, g_wrnd);

    float* biasenc;
    cudaGetSymbolAddress((void**)&biasenc, g_biasenc);

    // prep
    k_roundw<<<(NW_IN + NW_OUT + 255) / 256, 256>>>(in_proj_w, out_proj_w);
    k_sconv<<<dim3(KPAD, BB), NT>>>(x, sconv_w, sconv_b);
    k_mixprep<<<(DM * KPAD + 255) / 256, 256>>>(mixer_w);
    k_biasenc<<<32, 256>>>(emb, mixer_b);

    // encoder
    gemm_tf32<<<dim3(2, TOK / 128), 256>>>(xsr, mixw, biasenc, h, TOK, DM, KPAD);
    k_ln<<<TOK, DM>>>(h, nullptr, enc_ln_w, enc_ln_b, h);

    // mamba2 layers
    for (int l = 0; l < NL; l++) {
        gemm_tf32<<<dim3((DPROJ + 127) / 128, TOK / 128), 256>>>(
            h, wrnd + (size_t)l * DPROJ * DM, nullptr, zx, TOK, DPROJ, DM);
        k_dt<<<(TOK * NH + 255) / 256, 256>>>(dt_bias + l * NH, A_log + l * NH);
        k_conv3<<<dim3(5, BB, NT / TSEG), 128>>>(conv_w + (size_t)l * CONVD * 4,
                                                 conv_b + (size_t)l * CONVD);
        k_scan3<<<dim3(BB, 2), 256>>>(D_skip + l * NH);
        k_rms<<<TOK, 256>>>(norm_w + (size_t)l * DI);
        gemm_tf32<<<dim3(2, TOK / 128), 256>>>(
            y, wrnd + NW_IN + (size_t)l * DM * DI, nullptr, o, TOK, DM, DI);
        k_ln<<<TOK, DM>>>(o, h, ln_w + l * DM, ln_b + l * DM, h);
    }

    // head
    k_poolhead<<<BB, 256>>>(h1w, h1b, h2w, h2b, out);
}

// round 8
// speedup vs baseline: 1.2440x; 1.0512x over previous
#include <cuda_runtime.h>
#include <stdint.h>
#include <math.h>

#define BB     64
#define NCH    129
#define NT     200
#define DM     256
#define DSTATE 16
#define HD     32
#define NL     4
#define DI     512
#define NH     16
#define CONVD  544
#define DPROJ  1072
#define TOK    (BB*NT)   // 12800
#define KPAD   144
#define SMS    20
#define TTILE  20
#define TSEG   25

#define NW_IN  (NL*DPROJ*DM)
#define NW_OUT (NL*DM*DI)
#define GSMEM  (3*2*128*SMS*4)   // 61440 B dynamic smem for 3-stage gemm

// ---------------- scratch ---------------------------------------------------
__device__ float g_xsr[TOK*KPAD];
__device__ float g_mixw[DM*KPAD];
__device__ float g_biasenc[DM];
__device__ float g_h[TOK*DM];
__device__ float g_zx[TOK*DPROJ];
__device__ float g_xbc[TOK*CONVD];
__device__ float g_dt[TOK*NH];
__device__ float g_dA[TOK*NH];
__device__ float g_y[TOK*DI];
__device__ float g_o[TOK*DM];
__device__ float g_wrnd[NW_IN + NW_OUT];

// ---------------- helpers ---------------------------------------------------
__device__ __forceinline__ float siluf(float x) { return x / (1.f + expf(-x)); }

__device__ __forceinline__ float tf32r(float x) {
    uint32_t r; asm("cvt.rna.tf32.f32 %0, %1;" : "=r"(r) : "f"(x));
    return __uint_as_float(r);
}
__device__ __forceinline__ void mma_tf32(float* c, const uint32_t* a, const uint32_t* b) {
    asm volatile("mma.sync.aligned.m16n8k8.row.col.f32.tf32.tf32.f32 "
        "{%0,%1,%2,%3}, {%4,%5,%6,%7}, {%8,%9}, {%0,%1,%2,%3};"
        : "+f"(c[0]), "+f"(c[1]), "+f"(c[2]), "+f"(c[3])
        : "r"(a[0]), "r"(a[1]), "r"(a[2]), "r"(a[3]), "r"(b[0]), "r"(b[1]));
}
__device__ __forceinline__ void cpa16(uint32_t dst, const void* src, int sz) {
    asm volatile("cp.async.ca.shared.global [%0], [%1], 16, %2;"
                 :: "r"(dst), "l"(src), "r"(sz));
}

// ---------------- TF32 GEMM, 3-stage pipeline -------------------------------
__global__ void __launch_bounds__(256, 2)
gemm_tf32(const float* __restrict__ A, const float* __restrict__ W,
          const float* __restrict__ bias, float* __restrict__ C,
          int M, int N, int K) {
    extern __shared__ float dsm[];          // [3][128*SMS] A then [3][128*SMS] B
    const int bm = blockIdx.y * 128, bn = blockIdx.x * 128;
    const int tid = threadIdx.x, lane = tid & 31, warp = tid >> 5;
    const int wm = (warp & 1) * 64, wn = (warp >> 1) * 32;
    const int r0 = lane >> 2, c0 = lane & 3;

    float acc[4][4][4];
#pragma unroll
    for (int i = 0; i < 4; i++)
#pragma unroll
        for (int j = 0; j < 4; j++)
#pragma unroll
            for (int k = 0; k < 4; k++) acc[i][j][k] = 0.f;

    const int lr = tid >> 2, lc = (tid & 3) * 4;
    const float* Ap0 = A + (size_t)(bm + lr) * K + lc;
    const float* Ap1 = A + (size_t)(bm + lr + 64) * K + lc;
    const int bnr0 = bn + lr, bnr1 = bn + lr + 64;
    const float* Bp0 = W + (size_t)(bnr0 < N ? bnr0 : 0) * K + lc;
    const float* Bp1 = W + (size_t)(bnr1 < N ? bnr1 : 0) * K + lc;
    const int szb0 = bnr0 < N ? 16 : 0, szb1 = bnr1 < N ? 16 : 0;

    const uint32_t base = (uint32_t)__cvta_generic_to_shared(dsm);
    const uint32_t BUFB = 128u * SMS * 4u;
    const uint32_t dof0 = (uint32_t)(lr * SMS + lc) * 4u;
    const uint32_t dof1 = (uint32_t)((lr + 64) * SMS + lc) * 4u;

    const int KT = K >> 4;

#define LOADT(kt, buf)                                                   \
    do {                                                                 \
        int ko = (kt) * 16;                                              \
        uint32_t aA = base + (uint32_t)(buf) * BUFB;                     \
        uint32_t aB = base + (uint32_t)(3 + (buf)) * BUFB;               \
        cpa16(aA + dof0, Ap0 + ko, 16);                                  \
        cpa16(aA + dof1, Ap1 + ko, 16);                                  \
        cpa16(aB + dof0, Bp0 + ko, szb0);                                \
        cpa16(aB + dof1, Bp1 + ko, szb1);                                \
        asm volatile("cp.async.commit_group;");                          \
    } while (0)

    LOADT(0, 0);
    LOADT(1, 1);
    int ib = 2, cb = 0;
    for (int kt = 0; kt < KT; kt++) {
        if (kt < KT - 2) asm volatile("cp.async.wait_group 1;");
        else             asm volatile("cp.async.wait_group 0;");
        __syncthreads();
        if (kt + 2 < KT) {
            LOADT(kt + 2, ib);
            ib = (ib == 2) ? 0 : ib + 1;
        }
        const float* Asb = dsm + (size_t)cb * (128 * SMS);
        const float* Bsb = dsm + (size_t)(3 + cb) * (128 * SMS);
#pragma unroll
        for (int ks = 0; ks < 2; ks++) {
            uint32_t af[4][4], bf[4][2];
#pragma unroll
            for (int mi = 0; mi < 4; mi++) {
                const float* p = &Asb[(wm + mi * 16 + r0) * SMS + ks * 8 + c0];
                af[mi][0] = __float_as_uint(p[0]);
                af[mi][1] = __float_as_uint(p[8 * SMS]);
                af[mi][2] = __float_as_uint(p[4]);
                af[mi][3] = __float_as_uint(p[8 * SMS + 4]);
            }
#pragma unroll
            for (int nj = 0; nj < 4; nj++) {
                const float* p = &Bsb[(wn + nj * 8 + r0) * SMS + ks * 8 + c0];
                bf[nj][0] = __float_as_uint(p[0]);
                bf[nj][1] = __float_as_uint(p[4]);
            }
#pragma unroll
            for (int mi = 0; mi < 4; mi++)
#pragma unroll
                for (int nj = 0; nj < 4; nj++)
                    mma_tf32(acc[mi][nj], af[mi], bf[nj]);
        }
        cb = (cb == 2) ? 0 : cb + 1;
    }
#undef LOADT

#pragma unroll
    for (int mi = 0; mi < 4; mi++) {
        int row = bm + wm + mi * 16 + r0;
#pragma unroll
        for (int nj = 0; nj < 4; nj++) {
            int col = bn + wn + nj * 8 + c0 * 2;
            if (col < N) {
                float b0 = 0.f, b1 = 0.f;
                if (bias != nullptr) { b0 = bias[col]; b1 = bias[col + 1]; }
                float2 v0 = make_float2(acc[mi][nj][0] + b0, acc[mi][nj][1] + b1);
                float2 v1 = make_float2(acc[mi][nj][2] + b0, acc[mi][nj][3] + b1);
                *(float2*)&C[(size_t)row * N + col] = v0;
                *(float2*)&C[(size_t)(row + 8) * N + col] = v1;
            }
        }
    }
}

// ---------------- weight prep ------------------------------------------------
__global__ void k_roundw(const float* __restrict__ wi, const float* __restrict__ wo) {
    int idx = blockIdx.x * blockDim.x + threadIdx.x;
    if (idx < NW_IN) g_wrnd[idx] = tf32r(wi[idx]);
    else if (idx < NW_IN + NW_OUT) g_wrnd[idx] = tf32r(wo[idx - NW_IN]);
}

// ---------------- encoder ---------------------------------------------------
__global__ void k_sconv(const float* __restrict__ x, const float* __restrict__ w,
                        const float* __restrict__ bias) {
    int c = blockIdx.x, b = blockIdx.y, t = threadIdx.x;
    float v = 0.f;
    if (c < NCH) {
        const float* xr = x + (size_t)(b * NCH + c) * NT;
        float w0 = w[c * 3], w1 = w[c * 3 + 1], w2 = w[c * 3 + 2];
        float xm = (t > 0) ? xr[t - 1] : 0.f;
        float x0 = xr[t];
        float xp = (t < NT - 1) ? xr[t + 1] : 0.f;
        v = tf32r(xm * w0 + x0 * w1 + xp * w2 + bias[c]);
    }
    g_xsr[(size_t)(b * NT + t) * KPAD + c] = v;
}

__global__ void k_mixprep(const float* __restrict__ mw) {
    int idx = blockIdx.x * blockDim.x + threadIdx.x;
    if (idx >= DM * KPAD) return;
    int d = idx / KPAD, k = idx % KPAD;
    g_mixw[idx] = (k < NCH) ? tf32r(mw[d * NCH + k]) : 0.f;
}

// 1 block x 1024 thr: tid = d + 256*cgroup; coalesced over d
__global__ void k_biasenc(const float* __restrict__ emb, const float* __restrict__ mb) {
    __shared__ float sb[4][DM];
    int tid = threadIdx.x;
    int d = tid & 255, cg = tid >> 8;   // cg in 0..3
    float s = 0.f;
    for (int c = cg; c < NCH; c += 4) s += emb[c * DM + d];
    sb[cg][d] = s;
    __syncthreads();
    if (tid < DM)
        g_biasenc[tid] = mb[tid] +
            (sb[0][tid] + sb[1][tid] + sb[2][tid] + sb[3][tid]) * (1.f / NCH);
}

// ---------------- warp-per-row layernorm (no block barriers) -----------------
// grid TOK/8, block 256 (8 warps = 8 rows). lane covers cols [8l, 8l+8).
__global__ void k_ln(const float* __restrict__ in, const float* __restrict__ res,
                     const float* __restrict__ w, const float* __restrict__ b,
                     float* __restrict__ out) {
    int row = (blockIdx.x * 256 + threadIdx.x) >> 5;
    int lane = threadIdx.x & 31;
    const float4* ip = (const float4*)(in + (size_t)row * DM + lane * 8);
    float4 a0 = ip[0], a1 = ip[1];
    if (res != nullptr) {
        const float4* rp = (const float4*)(res + (size_t)row * DM + lane * 8);
        float4 q0 = rp[0], q1 = rp[1];
        a0.x += q0.x; a0.y += q0.y; a0.z += q0.z; a0.w += q0.w;
        a1.x += q1.x; a1.y += q1.y; a1.z += q1.z; a1.w += q1.w;
    }
    float v[8] = {a0.x, a0.y, a0.z, a0.w, a1.x, a1.y, a1.z, a1.w};
    float s = 0.f, s2 = 0.f;
#pragma unroll
    for (int i = 0; i < 8; i++) { s += v[i]; s2 = fmaf(v[i], v[i], s2); }
#pragma unroll
    for (int o = 16; o > 0; o >>= 1) {
        s  += __shfl_xor_sync(0xffffffffu, s,  o);
        s2 += __shfl_xor_sync(0xffffffffu, s2, o);
    }
    float mean = s * (1.f / DM);
    float var  = s2 * (1.f / DM) - mean * mean;
    float inv  = rsqrtf(var + 1e-5f);
    const float4* wp = (const float4*)(w + lane * 8);
    const float4* bp = (const float4*)(b + lane * 8);
    float4 w0 = wp[0], w1 = wp[1], b0 = bp[0], b1 = bp[1];
    float wv[8] = {w0.x, w0.y, w0.z, w0.w, w1.x, w1.y, w1.z, w1.w};
    float bv[8] = {b0.x, b0.y, b0.z, b0.w, b1.x, b1.y, b1.z, b1.w};
    float o8[8];
#pragma unroll
    for (int i = 0; i < 8; i++) o8[i] = tf32r((v[i] - mean) * inv * wv[i] + bv[i]);
    float4* op = (float4*)(out + (size_t)row * DM + lane * 8);
    op[0] = make_float4(o8[0], o8[1], o8[2], o8[3]);
    op[1] = make_float4(o8[4], o8[5], o8[6], o8[7]);
}

// ------- conv (time-parallel) + fused dt; grid (5, BB, NT/TSEG) --------------
__global__ void k_conv3(const float* __restrict__ cw, const float* __restrict__ cb,
                        const float* __restrict__ dtb, const float* __restrict__ alog) {
    const int c = blockIdx.x * 128 + threadIdx.x;
    const int b = blockIdx.y;
    const int t0 = blockIdx.z * TSEG;
    const bool cvalid = c < CONVD;
    float w0 = 0, w1 = 0, w2 = 0, w3 = 0, bc = 0;
    if (cvalid) { w0 = cw[c*4]; w1 = cw[c*4+1]; w2 = cw[c*4+2]; w3 = cw[c*4+3]; bc = cb[c]; }

    const float* zcol = g_zx + (size_t)(b * NT) * DPROJ + DI + c;
    float v[TSEG + 3];
#pragma unroll
    for (int i = 0; i < TSEG + 3; i++) {
        int t = t0 - 3 + i;
        v[i] = (cvalid && t >= 0) ? zcol[(size_t)t * DPROJ] : 0.f;
    }
    if (cvalid) {
        float* ocol = g_xbc + (size_t)(b * NT) * CONVD + c;
#pragma unroll
        for (int s = 0; s < TSEG; s++) {
            float o = bc + w0 * v[s] + w1 * v[s + 1] + w2 * v[s + 2] + w3 * v[s + 3];
            ocol[(size_t)(t0 + s) * CONVD] = siluf(o);
        }
    }
    // fused dt/dA for this (b, t-segment): 16 threads of block x==0
    if (blockIdx.x == 0 && threadIdx.x < NH) {
        const int h = threadIdx.x;
        const float db = dtb[h], Ae = expf(alog[h]);
        const float* dcol = g_zx + (size_t)(b * NT) * DPROJ + DI + CONVD + h;
#pragma unroll
        for (int s = 0; s < TSEG; s++) {
            float raw = dcol[(size_t)(t0 + s) * DPROJ] + db;
            float d = raw > 20.f ? raw : log1pf(expf(raw));
            int bt = b * NT + t0 + s;
            g_dt[bt * NH + h] = d;
            g_dA[bt * NH + h] = expf(-d * Ae);
        }
    }
}

// -------- time-tiled SSM scan with fused silu(z) gate ------------------------
__global__ void k_scan3(const float* __restrict__ Dsk) {
    const int b = blockIdx.x, half = blockIdx.y;
    const int tid = threadIdx.x;                // 256
    const int h = tid >> 4, p = (tid & 15) + half * 16;
    __shared__ float sB[TTILE][16], sC[TTILE][16];
    __shared__ float sA[TTILE][16], sT[TTILE][16];

    float st[DSTATE];
#pragma unroll
    for (int n = 0; n < DSTATE; n++) st[n] = 0.f;
    const float Dh = Dsk[h];
    const int base = b * NT;
    const size_t xoff = (size_t)h * HD + p;

    for (int t0 = 0; t0 < NT; t0 += TTILE) {
        float xv[TTILE], zv[TTILE];
#pragma unroll
        for (int tl = 0; tl < TTILE; tl++) {
            xv[tl] = __ldg(g_xbc + (size_t)(base + t0 + tl) * CONVD + xoff);
            zv[tl] = __ldg(g_zx + (size_t)(base + t0 + tl) * DPROJ + xoff);
        }

        __syncthreads();
#pragma unroll
        for (int i = tid; i < TTILE * 64; i += 256) {
            const int tl = i >> 6, j = i & 63;
            const int bt = base + t0 + tl;
            if (j < 32) {
                float v = g_xbc[(size_t)bt * CONVD + DI + j];
                if (j < 16) sB[tl][j] = v; else sC[tl][j - 16] = v;
            } else if (j < 48) {
                sA[tl][j - 32] = g_dA[bt * NH + (j - 32)];
            } else {
                sT[tl][j - 48] = g_dt[bt * NH + (j - 48)];
            }
        }
        __syncthreads();

#pragma unroll
        for (int tl = 0; tl < TTILE; tl++) {
            const float xp = xv[tl];
            const float dAh = sA[tl][h];
            const float dtx = sT[tl][h] * xp;
            float a0 = 0.f, a1 = 0.f;
#pragma unroll
            for (int n = 0; n < DSTATE; n += 2) {
                st[n]     = fmaf(dAh, st[n],     dtx * sB[tl][n]);
                st[n + 1] = fmaf(dAh, st[n + 1], dtx * sB[tl][n + 1]);
                a0 = fmaf(st[n],     sC[tl][n],     a0);
                a1 = fmaf(st[n + 1], sC[tl][n + 1], a1);
            }
            g_y[(size_t)(base + t0 + tl) * DI + xoff] =
                (a0 + a1 + xp * Dh) * siluf(zv[tl]);
        }
    }
}

// ---------------- warp-per-row RMSNorm (512 cols; lane covers 16) ------------
__global__ void k_rms(const float* __restrict__ nw) {
    int row = (blockIdx.x * 256 + threadIdx.x) >> 5;
    int lane = threadIdx.x & 31;
    float* yp = g_y + (size_t)row * DI + lane * 16;
    float4 y0 = ((float4*)yp)[0], y1 = ((float4*)yp)[1];
    float4 y2 = ((float4*)yp)[2], y3 = ((float4*)yp)[3];
    float v[16] = {y0.x,y0.y,y0.z,y0.w, y1.x,y1.y,y1.z,y1.w,
                   y2.x,y2.y,y2.z,y2.w, y3.x,y3.y,y3.z,y3.w};
    float s2 = 0.f;
#pragma unroll
    for (int i = 0; i < 16; i++) s2 = fmaf(v[i], v[i], s2);
#pragma unroll
    for (int o = 16; o > 0; o >>= 1) s2 += __shfl_xor_sync(0xffffffffu, s2, o);
    float sc = rsqrtf(s2 * (1.f / DI) + 1e-5f);
    const float4* wp = (const float4*)(nw + lane * 16);
    float4 w0 = wp[0], w1 = wp[1], w2 = wp[2], w3 = wp[3];
    float wv[16] = {w0.x,w0.y,w0.z,w0.w, w1.x,w1.y,w1.z,w1.w,
                    w2.x,w2.y,w2.z,w2.w, w3.x,w3.y,w3.z,w3.w};
    float o16[16];
#pragma unroll
    for (int i = 0; i < 16; i++) o16[i] = tf32r(v[i] * sc * wv[i]);
    ((float4*)yp)[0] = make_float4(o16[0], o16[1], o16[2], o16[3]);
    ((float4*)yp)[1] = make_float4(o16[4], o16[5], o16[6], o16[7]);
    ((float4*)yp)[2] = make_float4(o16[8], o16[9], o16[10], o16[11]);
    ((float4*)yp)[3] = make_float4(o16[12], o16[13], o16[14], o16[15]);
}

// ---------------- fused pool + head ------------------------------------------
__global__ void k_poolhead(const float* __restrict__ w1, const float* __restrict__ b1,
                           const float* __restrict__ w2, const float* __restrict__ b2,
                           float* __restrict__ out) {
    __shared__ float sp[DM];
    __shared__ float sh[4];
    int b = blockIdx.x, tid = threadIdx.x;    // 256
    float s = 0.f;
    for (int t = 0; t < NT; t++) s += g_h[(size_t)(b * NT + t) * DM + tid];
    sp[tid] = s * (1.f / NT);
    __syncthreads();
    if (tid < 128) {
        float acc = b1[tid];
        const float* wr = w1 + tid * DM;
#pragma unroll 8
        for (int k = 0; k < DM; k++) acc = fmaf(sp[k], wr[k], acc);
        float r = fmaxf(acc, 0.f) * w2[tid];
#pragma unroll
        for (int o = 16; o > 0; o >>= 1) r += __shfl_xor_sync(0xffffffffu, r, o);
        int lane = tid & 31, wid = tid >> 5;
        if (lane == 0) sh[wid] = r;
    }
    __syncthreads();
    if (tid == 0) out[b] = sh[0] + sh[1] + sh[2] + sh[3] + b2[0];
}

// ---------------- launch -----------------------------------------------------
extern "C" void kernel_launch(void* const* d_in, const int* in_sizes, int n_in,
                              void* d_out, int out_size) {
    const float* x         = (const float*)d_in[0];
    const float* emb       = (const float*)d_in[1];
    const float* sconv_w   = (const float*)d_in[2];
    const float* sconv_b   = (const float*)d_in[3];
    const float* mixer_w   = (const float*)d_in[4];
    const float* mixer_b   = (const float*)d_in[5];
    const float* enc_ln_w  = (const float*)d_in[6];
    const float* enc_ln_b  = (const float*)d_in[7];
    const float* in_proj_w = (const float*)d_in[8];
    const float* conv_w    = (const float*)d_in[9];
    const float* conv_b    = (const float*)d_in[10];
    const float* dt_bias   = (const float*)d_in[11];
    const float* A_log     = (const float*)d_in[12];
    const float* D_skip    = (const float*)d_in[13];
    const float* norm_w    = (const float*)d_in[14];
    const float* out_proj_w= (const float*)d_in[15];
    const float* ln_w      = (const float*)d_in[16];
    const float* ln_b      = (const float*)d_in[17];
    const float* h1w       = (const float*)d_in[18];
    const float* h1b       = (const float*)d_in[19];
    const float* h2w       = (const float*)d_in[20];
    const float* h2b       = (const float*)d_in[21];
    float* out = (float*)d_out;

    float *xsr, *mixw, *biasenc, *h, *zx, *y, *o, *wrnd;
    cudaGetSymbolAddress((void**)&xsr,     g_xsr);
    cudaGetSymbolAddress((void**)&mixw,    g_mixw);
    cudaGetSymbolAddress((void**)&biasenc, g_biasenc);
    cudaGetSymbolAddress((void**)&h,       g_h);
    cudaGetSymbolAddress((void**)&zx,      g_zx);
    cudaGetSymbolAddress((void**)&y,       g_y);
    cudaGetSymbolAddress((void**)&o,       g_o);
    cudaGetSymbolAddress((void**)&wrnd,    g_wrnd);

    cudaFuncSetAttribute(gemm_tf32, cudaFuncAttributeMaxDynamicSharedMemorySize, GSMEM);

    // prep
    k_roundw<<<(NW_IN + NW_OUT + 255) / 256, 256>>>(in_proj_w, out_proj_w);
    k_sconv<<<dim3(KPAD, BB), NT>>>(x, sconv_w, sconv_b);
    k_mixprep<<<(DM * KPAD + 255) / 256, 256>>>(mixer_w);
    k_biasenc<<<1, 1024>>>(emb, mixer_b);

    // encoder
    gemm_tf32<<<dim3(2, TOK / 128), 256, GSMEM>>>(xsr, mixw, biasenc, h, TOK, DM, KPAD);
    k_ln<<<TOK / 8, 256>>>(h, nullptr, enc_ln_w, enc_ln_b, h);

    // mamba2 layers
    for (int l = 0; l < NL; l++) {
        gemm_tf32<<<dim3((DPROJ + 127) / 128, TOK / 128), 256, GSMEM>>>(
            h, wrnd + (size_t)l * DPROJ * DM, nullptr, zx, TOK, DPROJ, DM);
        k_conv3<<<dim3(5, BB, NT / TSEG), 128>>>(conv_w + (size_t)l * CONVD * 4,
                                                 conv_b + (size_t)l * CONVD,
                                                 dt_bias + l * NH, A_log + l * NH);
        k_scan3<<<dim3(BB, 2), 256>>>(D_skip + l * NH);
        k_rms<<<TOK / 8, 256>>>(norm_w + (size_t)l * DI);
        gemm_tf32<<<dim3(2, TOK / 128), 256, GSMEM>>>(
            y, wrnd + NW_IN + (size_t)l * DM * DI, nullptr, o, TOK, DM, DI);
        k_ln<<<TOK / 8, 256>>>(o, h, ln_w + l * DM, ln_b + l * DM, h);
    }

    // head
    k_poolhead<<<BB, 256>>>(h1w, h1b, h2w, h2b, out);
}